// round 10
// baseline (speedup 1.0000x reference)
#include <cuda_runtime.h>
#include <cuda_fp16.h>
#include <math.h>

#define GRES 128
#define NPIX 16384

// Fused trilinear table: T[a2][a1][a0] -> uint4 (6 halves + pad). 33.5 MB.
__device__ uint4 g_T[GRES * GRES * GRES];
// s-interleaved fp16 plane streams: [g(2)][sg(3)][c(16)][px] = half2(s0,s1). 6.3 MB
__device__ unsigned g_pH[2 * 3 * 16 * NPIX];
// s-interleaved fp16 line2 rows: [sg][c][a0] = half2(s0,s1). 24 KB
__device__ unsigned g_L2H[3 * 16 * GRES];

__device__ __forceinline__ __half2 u2h(unsigned u) {
    return *reinterpret_cast<__half2*>(&u);
}
__device__ __forceinline__ unsigned h2u(__half2 h) {
    return *reinterpret_cast<unsigned*>(&h);
}

// ---------------------------------------------------------------------------
// Prep: s-interleaved fp16 streams for plane groups 0,1.
// ---------------------------------------------------------------------------
__global__ void prep_ph(const float* __restrict__ planes) {
    int o = blockIdx.x * 256 + threadIdx.x;          // over 786432 pixel-pairs
    if (o >= 2 * 3 * 16 * (NPIX / 2)) return;
    int pp = o & 8191;
    int t  = o >> 13;
    int c  = t & 15;  t >>= 4;
    int sg = t % 3;
    int g  = t / 3;
    const float2* s0 = (const float2*)(planes + ((size_t)(g * 96 + (2 * sg) * 16 + c) << 14)) + pp;
    const float2* s1 = (const float2*)(planes + ((size_t)(g * 96 + (2 * sg + 1) * 16 + c) << 14)) + pp;
    float2 v0 = __ldg(s0);
    float2 v1 = __ldg(s1);
    uint2 q;
    q.x = h2u(__floats2half2_rn(v0.x, v1.x));
    q.y = h2u(__floats2half2_rn(v0.y, v1.y));
    reinterpret_cast<uint2*>(g_pH)[((g * 3 + sg) * 16 + c) * 8192 + pp] = q;
}

__global__ void prep_lh(const float* __restrict__ lines) {
    int o = blockIdx.x * 256 + threadIdx.x;          // over 6144
    if (o >= 3 * 16 * GRES) return;
    int x = o & 127;
    int c = (o >> 7) & 15;
    int sg = o >> 11;
    float v0 = __ldg(&lines[(size_t)(192 + (2 * sg) * 16 + c) * GRES + x]);
    float v1 = __ldg(&lines[(size_t)(192 + (2 * sg + 1) * 16 + c) * GRES + x]);
    g_L2H[o] = h2u(__floats2half2_rn(v0, v1));
}

// ---------------------------------------------------------------------------
// Voxelize, all-fp16 HFMA2, pipelined, all 3 s-groups in one block:
//   T[a2][a1][a0][s] = sum_c plane0[sc][a1][a0]*line0[sc][a2]
//                    + plane1[sc][a2][a0]*line1[sc][a1]
//                    + plane2[sc][a2][a1]*line2[sc][a0]
// Block = 384 thr = 3 sg-groups x 4 a1-warps. Per warp per c: 6 LDG.128
// (prefetched one c ahead) + 48 HFMA2 + 3 smem reads. Epilogue assembles
// full uint4 records via smem -> coalesced STG.128 (no write amplification).
// ---------------------------------------------------------------------------
__global__ __launch_bounds__(384)
void voxelize(const float* __restrict__ planes, const float* __restrict__ lines) {
    __shared__ __align__(16) __half2 s_l0[3][16][4];      // [sg][c][d]
    __shared__ __align__(16) __half2 s_l1[3][16][4];      // [sg][c][wid]
    __shared__ __align__(16) __half2 s_p2[3][16][4][4];   // [sg][c][wid][d]
    __shared__ unsigned s_res[3][4][4][GRES];             // [sg][d][wid][a0] 32KB

    const int tid  = threadIdx.x;
    const int sgw  = tid >> 7;             // s-group 0..2
    const int wg   = tid & 127;
    const int lane = wg & 31;
    const int wid  = wg >> 5;              // local a1
    const int a1b  = blockIdx.x * 4;
    const int a2b  = blockIdx.y * 4;
    const int a1   = a1b + wid;
    const int a0   = lane * 4;

    // ---- one-time staging of scalar splats ----
    if (tid < 384) {
        int i = tid;                       // 0..191 -> l0 ; 192..383 -> l1
        int e = i % 192;
        int d = e & 3, c = (e >> 2) & 15, sg = e >> 6;
        int sc0 = (2 * sg) * 16 + c, sc1 = sc0 + 16;
        if (i < 192) {
            float v0 = lines[(size_t)sc0 * GRES + a2b + d];
            float v1 = lines[(size_t)sc1 * GRES + a2b + d];
            s_l0[sg][c][d] = __floats2half2_rn(v0, v1);
        } else {
            float v0 = lines[(size_t)(96 + sc0) * GRES + a1b + d];
            float v1 = lines[(size_t)(96 + sc1) * GRES + a1b + d];
            s_l1[sg][c][d] = __floats2half2_rn(v0, v1);
        }
    }
    for (int i = tid; i < 768; i += 384) {   // p2: [sg][c][w][d]
        int d = i & 3, w = (i >> 2) & 3, c = (i >> 4) & 15, sg = i >> 8;
        int sc0 = (2 * sg) * 16 + c, sc1 = sc0 + 16;
        float v0 = planes[(size_t)(192 + sc0) * NPIX + (a2b + d) * GRES + (a1b + w)];
        float v1 = planes[(size_t)(192 + sc1) * NPIX + (a2b + d) * GRES + (a1b + w)];
        s_p2[sg][c][w][d] = __floats2half2_rn(v0, v1);
    }
    __syncthreads();

    __half2 acc[4][4];                     // [d = a2 local][j = a0 offset]
    #pragma unroll
    for (int d = 0; d < 4; d++)
        #pragma unroll
        for (int j = 0; j < 4; j++)
            acc[d][j] = __floats2half2_rn(0.0f, 0.0f);

    const unsigned* __restrict__ P0b = g_pH + (((size_t)sgw * 16) << 14);
    const unsigned* __restrict__ P1b = g_pH + (((size_t)(48 + sgw * 16)) << 14);
    const unsigned* __restrict__ L2b = g_L2H + sgw * 16 * GRES;

    // ---- software-pipelined main loop (prefetch c+1 before compute c) ----
    uint4 P0a, L2a, P1a0, P1a1, P1a2, P1a3;
    P0a  = __ldg((const uint4*)(P0b + a1 * GRES + a0));
    L2a  = __ldg((const uint4*)(L2b + a0));
    P1a0 = __ldg((const uint4*)(P1b + (a2b + 0) * GRES + a0));
    P1a1 = __ldg((const uint4*)(P1b + (a2b + 1) * GRES + a0));
    P1a2 = __ldg((const uint4*)(P1b + (a2b + 2) * GRES + a0));
    P1a3 = __ldg((const uint4*)(P1b + (a2b + 3) * GRES + a0));

    #pragma unroll
    for (int c = 0; c < 16; c++) {
        uint4 P0n, L2n, P1n0, P1n1, P1n2, P1n3;
        if (c < 15) {
            const size_t off = ((size_t)(c + 1)) << 14;
            P0n  = __ldg((const uint4*)(P0b + off + a1 * GRES + a0));
            L2n  = __ldg((const uint4*)(L2b + (c + 1) * GRES + a0));
            P1n0 = __ldg((const uint4*)(P1b + off + (a2b + 0) * GRES + a0));
            P1n1 = __ldg((const uint4*)(P1b + off + (a2b + 1) * GRES + a0));
            P1n2 = __ldg((const uint4*)(P1b + off + (a2b + 2) * GRES + a0));
            P1n3 = __ldg((const uint4*)(P1b + off + (a2b + 3) * GRES + a0));
        }

        const __half2 p0j[4] = {u2h(P0a.x), u2h(P0a.y), u2h(P0a.z), u2h(P0a.w)};
        const __half2 l2j[4] = {u2h(L2a.x), u2h(L2a.y), u2h(L2a.z), u2h(L2a.w)};
        uint4 l0u = *(const uint4*)&s_l0[sgw][c][0];        // warp-uniform
        uint4 p2u = *(const uint4*)&s_p2[sgw][c][wid][0];   // warp-uniform
        const __half2 l1w = s_l1[sgw][c][wid];              // warp-uniform
        const __half2 l0d[4] = {u2h(l0u.x), u2h(l0u.y), u2h(l0u.z), u2h(l0u.w)};
        const __half2 p2d[4] = {u2h(p2u.x), u2h(p2u.y), u2h(p2u.z), u2h(p2u.w)};
        const uint4 P1arr[4] = {P1a0, P1a1, P1a2, P1a3};

        #pragma unroll
        for (int d = 0; d < 4; d++) {
            const __half2 p1j[4] = {u2h(P1arr[d].x), u2h(P1arr[d].y),
                                    u2h(P1arr[d].z), u2h(P1arr[d].w)};
            #pragma unroll
            for (int j = 0; j < 4; j++) {
                acc[d][j] = __hfma2(p0j[j], l0d[d], acc[d][j]);
                acc[d][j] = __hfma2(p1j[j], l1w,    acc[d][j]);
                acc[d][j] = __hfma2(l2j[j], p2d[d], acc[d][j]);
            }
        }

        P0a = P0n; L2a = L2n;
        P1a0 = P1n0; P1a1 = P1n1; P1a2 = P1n2; P1a3 = P1n3;
    }

    // ---- epilogue: smem transpose -> coalesced STG.128 full records ----
    #pragma unroll
    for (int d = 0; d < 4; d++) {
        uint4 q;
        q.x = h2u(acc[d][0]); q.y = h2u(acc[d][1]);
        q.z = h2u(acc[d][2]); q.w = h2u(acc[d][3]);
        *(uint4*)&s_res[sgw][d][wid][a0] = q;
    }
    __syncthreads();

    for (int v = tid; v < 2048; v += 384) {
        int x = v & 127;
        int w = (v >> 7) & 3;
        int d = v >> 9;
        uint4 q;
        q.x = s_res[0][d][w][x];
        q.y = s_res[1][d][w][x];
        q.z = s_res[2][d][w][x];
        q.w = 0u;
        g_T[(((size_t)(a2b + d)) * GRES + (a1b + w)) * GRES + x] = q;
    }
}

// ---------------------------------------------------------------------------
// Sample + Rodrigues: one thread per point; 8 LDG.128 trilinear gathers.
// ---------------------------------------------------------------------------
__device__ __forceinline__ void unp6(uint4 q, float f[6]) {
    float2 a = __half22float2(u2h(q.x));
    float2 b = __half22float2(u2h(q.y));
    float2 c = __half22float2(u2h(q.z));
    f[0] = a.x; f[1] = a.y; f[2] = b.x; f[3] = b.y; f[4] = c.x; f[5] = c.y;
}

__global__ __launch_bounds__(256)
void sample_warp(const float* __restrict__ xyz, const float* __restrict__ vd,
                 const float* __restrict__ aabb, float* __restrict__ out,
                 int npts) {
    int pt = blockIdx.x * 256 + threadIdx.x;
    if (pt >= npts) return;

    const float X0 = xyz[pt * 3 + 0], X1 = xyz[pt * 3 + 1], X2 = xyz[pt * 3 + 2];
    const float Pc[3] = {X0, X1, X2};

    int ii[2][3];
    float w[3];
    #pragma unroll
    for (int d = 0; d < 3; d++) {
        float lo = __ldg(&aabb[d]), hi = __ldg(&aabb[3 + d]);
        float xn = (Pc[d] - lo) * (2.0f / (hi - lo)) - 1.0f;
        float f = fmaf(xn, 63.5f, 63.5f);
        f = fminf(fmaxf(f, 0.0f), 127.0f);
        float ff = floorf(f);
        ii[0][d] = (int)ff;
        ii[1][d] = min(ii[0][d] + 1, GRES - 1);
        w[d] = f - ff;
    }

    float f[2][2][2][6];
    #pragma unroll
    for (int c2 = 0; c2 < 2; c2++)
        #pragma unroll
        for (int c1 = 0; c1 < 2; c1++)
            #pragma unroll
            for (int c0 = 0; c0 < 2; c0++) {
                uint4 q = __ldg(&g_T[((size_t)ii[c2][2] * GRES + ii[c1][1]) * GRES
                                     + ii[c0][0]]);
                unp6(q, f[c2][c1][c0]);
            }

    float bw[6];
    #pragma unroll
    for (int j = 0; j < 6; j++) {
        float e00 = fmaf(w[0], f[0][0][1][j] - f[0][0][0][j], f[0][0][0][j]);
        float e01 = fmaf(w[0], f[0][1][1][j] - f[0][1][0][j], f[0][1][0][j]);
        float e10 = fmaf(w[0], f[1][0][1][j] - f[1][0][0][j], f[1][0][0][j]);
        float e11 = fmaf(w[0], f[1][1][1][j] - f[1][1][0][j], f[1][1][0][j]);
        float g0  = fmaf(w[1], e01 - e00, e00);
        float g1  = fmaf(w[1], e11 - e10, e10);
        bw[j] = fmaf(w[2], g1 - g0, g0);
    }

    float w0 = bw[0], w1 = bw[1], w2 = bw[2];
    float v0 = bw[3], v1 = bw[4], v2 = bw[5];

    float th2 = fmaf(w0, w0, fmaf(w1, w1, w2 * w2));
    th2 = fmaxf(th2, 1e-6f);
    float th  = sqrtf(th2);
    float inv = 1.0f / th;
    w0 *= inv; w1 *= inv; w2 *= inv;
    v0 *= inv; v1 *= inv; v2 *= inv;

    float q  = fmaf(w0, w0, fmaf(w1, w1, w2 * w2));
    float s  = sinf(th);
    float co = cosf(th);
    float cm = 1.0f - co;
    float ts = th - s;

    float rD = 1.0f - cm * q;
    float pD = th - ts * q;

    float D0 = vd[pt * 3 + 0], D1 = vd[pt * 3 + 1], D2 = vd[pt * 3 + 2];

    float wdV = fmaf(w0, v0, fmaf(w1, v1, w2 * v2));
    float t0 = pD * v0 + cm * (w1 * v2 - w2 * v1) + ts * w0 * wdV;
    float t1 = pD * v1 + cm * (w2 * v0 - w0 * v2) + ts * w1 * wdV;
    float t2 = pD * v2 + cm * (w0 * v1 - w1 * v0) + ts * w2 * wdV;

    float wdX = fmaf(w0, X0, fmaf(w1, X1, w2 * X2));
    float xw0 = rD * X0 + s * (w1 * X2 - w2 * X1) + cm * w0 * wdX + t0;
    float xw1 = rD * X1 + s * (w2 * X0 - w0 * X2) + cm * w1 * wdX + t1;
    float xw2 = rD * X2 + s * (w0 * X1 - w1 * X0) + cm * w2 * wdX + t2;

    float wdD = fmaf(w0, D0, fmaf(w1, D1, w2 * D2));
    float vw0 = rD * D0 + s * (w1 * D2 - w2 * D1) + cm * w0 * wdD;
    float vw1 = rD * D1 + s * (w2 * D0 - w0 * D2) + cm * w1 * wdD;
    float vw2 = rD * D2 + s * (w0 * D1 - w1 * D0) + cm * w2 * wdD;

    out[(size_t)pt * 3 + 0] = xw0;
    out[(size_t)pt * 3 + 1] = xw1;
    out[(size_t)pt * 3 + 2] = xw2;
    size_t off = (size_t)npts * 3;
    out[off + (size_t)pt * 3 + 0] = vw0;
    out[off + (size_t)pt * 3 + 1] = vw1;
    out[off + (size_t)pt * 3 + 2] = vw2;
}

// ---------------------------------------------------------------------------
extern "C" void kernel_launch(void* const* d_in, const int* in_sizes, int n_in,
                              void* d_out, int out_size) {
    const float* xyz    = (const float*)d_in[0];
    const float* vdirs  = (const float*)d_in[1];
    const float* planes = (const float*)d_in[4];
    const float* lines  = (const float*)d_in[5];
    const float* aabb   = (const float*)d_in[6];
    float* out = (float*)d_out;

    const int npts = in_sizes[0] / 3;

    prep_ph<<<(2 * 3 * 16 * (NPIX / 2) + 255) / 256, 256>>>(planes);
    prep_lh<<<(3 * 16 * GRES + 255) / 256, 256>>>(lines);
    voxelize<<<dim3(GRES / 4, GRES / 4), 384>>>(planes, lines);
    sample_warp<<<(npts + 255) / 256, 256>>>(xyz, vdirs, aabb, out, npts);
}

// round 11
// speedup vs baseline: 1.1365x; 1.1365x over previous
#include <cuda_runtime.h>
#include <cuda_fp16.h>
#include <math.h>

#define GRES 128
#define NPIX 16384

// Fused trilinear table: T[a2][a1][a0] -> uint4 (6 halves + pad). 33.5 MB.
__device__ uint4 g_T[GRES * GRES * GRES];
// s-interleaved fp16 plane streams: [g(2)][sg(3)][c(16)][px] = half2(s0,s1). 6.3 MB
__device__ unsigned g_pH[2 * 3 * 16 * NPIX];
// s-interleaved fp16 line2 rows: [sg][c][a0] = half2(s0,s1). 24 KB
__device__ unsigned g_L2H[3 * 16 * GRES];

__device__ __forceinline__ __half2 u2h(unsigned u) {
    return *reinterpret_cast<__half2*>(&u);
}
__device__ __forceinline__ unsigned h2u(__half2 h) {
    return *reinterpret_cast<unsigned*>(&h);
}

// ---------------------------------------------------------------------------
// Prep: s-interleaved fp16 streams for plane groups 0,1.
// ---------------------------------------------------------------------------
__global__ void prep_ph(const float* __restrict__ planes) {
    int o = blockIdx.x * 256 + threadIdx.x;          // over 786432 pixel-pairs
    if (o >= 2 * 3 * 16 * (NPIX / 2)) return;
    int pp = o & 8191;
    int t  = o >> 13;
    int c  = t & 15;  t >>= 4;
    int sg = t % 3;
    int g  = t / 3;
    const float2* s0 = (const float2*)(planes + ((size_t)(g * 96 + (2 * sg) * 16 + c) << 14)) + pp;
    const float2* s1 = (const float2*)(planes + ((size_t)(g * 96 + (2 * sg + 1) * 16 + c) << 14)) + pp;
    float2 v0 = __ldg(s0);
    float2 v1 = __ldg(s1);
    uint2 q;
    q.x = h2u(__floats2half2_rn(v0.x, v1.x));
    q.y = h2u(__floats2half2_rn(v0.y, v1.y));
    reinterpret_cast<uint2*>(g_pH)[((g * 3 + sg) * 16 + c) * 8192 + pp] = q;
}

__global__ void prep_lh(const float* __restrict__ lines) {
    int o = blockIdx.x * 256 + threadIdx.x;          // over 6144
    if (o >= 3 * 16 * GRES) return;
    int x = o & 127;
    int c = (o >> 7) & 15;
    int sg = o >> 11;
    float v0 = __ldg(&lines[(size_t)(192 + (2 * sg) * 16 + c) * GRES + x]);
    float v1 = __ldg(&lines[(size_t)(192 + (2 * sg + 1) * 16 + c) * GRES + x]);
    g_L2H[o] = h2u(__floats2half2_rn(v0, v1));
}

// ---------------------------------------------------------------------------
// Voxelize, all-fp16 HFMA2, s-interleaved (grid.z = sg), PIPELINED:
//   T[a2][a1][a0][s] = sum_c plane0[sc][a1][a0]*line0[sc][a2]
//                    + plane1[sc][a2][a0]*line1[sc][a1]
//                    + plane2[sc][a2][a1]*line2[sc][a0]
// Round-9 shape (128 thr = 4 warps x 4-wide a2, tiny smem, strided epilogue)
// + double-buffered prefetch: iteration c+1's 6 LDG.128 issue before c's
// 48 HFMA2, hiding L2-hit latency at unchanged occupancy.
// ---------------------------------------------------------------------------
__global__ __launch_bounds__(128)
void voxelize(const float* __restrict__ planes, const float* __restrict__ lines) {
    __shared__ __align__(16) __half2 s_l0[16][4];      // [c][d]   line0 splat
    __shared__ __align__(16) __half2 s_l1[16][4];      // [c][wid] line1 splat
    __shared__ __align__(16) __half2 s_p2[16][4][4];   // [c][wid][d] plane2 splat

    const int tid  = threadIdx.x;
    const int lane = tid & 31;
    const int wid  = tid >> 5;             // local a1
    const int a1b  = blockIdx.x * 4;
    const int a2b  = blockIdx.y * 4;
    const int sg   = blockIdx.z;           // s-group: s = 2sg, 2sg+1
    const int a1   = a1b + wid;
    const int a0   = lane * 4;

    // ---- one-time staging of scalar splats (fp32 inputs -> half2 pairs) ----
    {
        int i = tid;                                   // 128 entries: l0 | l1
        int c = (i >> 2) & 15, d = i & 3;
        int sc0 = (2 * sg) * 16 + c, sc1 = sc0 + 16;
        if (i < 64) {
            float v0 = lines[(size_t)sc0 * GRES + a2b + d];
            float v1 = lines[(size_t)sc1 * GRES + a2b + d];
            s_l0[c][d] = __floats2half2_rn(v0, v1);
        } else {
            float v0 = lines[(size_t)(96 + sc0) * GRES + a1b + d];
            float v1 = lines[(size_t)(96 + sc1) * GRES + a1b + d];
            s_l1[c][d] = __floats2half2_rn(v0, v1);
        }
    }
    for (int i = tid; i < 256; i += 128) {             // p2: [c][w][d]
        int c = i >> 4, w = (i >> 2) & 3, d = i & 3;
        int sc0 = (2 * sg) * 16 + c, sc1 = sc0 + 16;
        float v0 = planes[(size_t)(192 + sc0) * NPIX + (a2b + d) * GRES + (a1b + w)];
        float v1 = planes[(size_t)(192 + sc1) * NPIX + (a2b + d) * GRES + (a1b + w)];
        s_p2[c][w][d] = __floats2half2_rn(v0, v1);
    }
    __syncthreads();

    __half2 acc[4][4];                     // [d = a2 local][j = a0 offset]
    #pragma unroll
    for (int d = 0; d < 4; d++)
        #pragma unroll
        for (int j = 0; j < 4; j++)
            acc[d][j] = __floats2half2_rn(0.0f, 0.0f);

    const unsigned* __restrict__ P0b = g_pH + (((size_t)sg * 16) << 14);
    const unsigned* __restrict__ P1b = g_pH + (((size_t)(48 + sg * 16)) << 14);
    const unsigned* __restrict__ L2b = g_L2H + sg * 16 * GRES;

    // ---- software-pipelined main loop ----
    uint4 P0a, L2a, P1a0, P1a1, P1a2, P1a3;
    P0a  = __ldg((const uint4*)(P0b + a1 * GRES + a0));
    L2a  = __ldg((const uint4*)(L2b + a0));
    P1a0 = __ldg((const uint4*)(P1b + (a2b + 0) * GRES + a0));
    P1a1 = __ldg((const uint4*)(P1b + (a2b + 1) * GRES + a0));
    P1a2 = __ldg((const uint4*)(P1b + (a2b + 2) * GRES + a0));
    P1a3 = __ldg((const uint4*)(P1b + (a2b + 3) * GRES + a0));

    #pragma unroll
    for (int c = 0; c < 16; c++) {
        uint4 P0n, L2n, P1n0, P1n1, P1n2, P1n3;
        if (c < 15) {
            const size_t off = ((size_t)(c + 1)) << 14;
            P0n  = __ldg((const uint4*)(P0b + off + a1 * GRES + a0));
            L2n  = __ldg((const uint4*)(L2b + (c + 1) * GRES + a0));
            P1n0 = __ldg((const uint4*)(P1b + off + (a2b + 0) * GRES + a0));
            P1n1 = __ldg((const uint4*)(P1b + off + (a2b + 1) * GRES + a0));
            P1n2 = __ldg((const uint4*)(P1b + off + (a2b + 2) * GRES + a0));
            P1n3 = __ldg((const uint4*)(P1b + off + (a2b + 3) * GRES + a0));
        }

        const __half2 p0j[4] = {u2h(P0a.x), u2h(P0a.y), u2h(P0a.z), u2h(P0a.w)};
        const __half2 l2j[4] = {u2h(L2a.x), u2h(L2a.y), u2h(L2a.z), u2h(L2a.w)};
        uint4 l0u = *(const uint4*)&s_l0[c][0];        // warp-uniform
        uint4 p2u = *(const uint4*)&s_p2[c][wid][0];   // warp-uniform
        const __half2 l1w = s_l1[c][wid];              // warp-uniform
        const __half2 l0d[4] = {u2h(l0u.x), u2h(l0u.y), u2h(l0u.z), u2h(l0u.w)};
        const __half2 p2d[4] = {u2h(p2u.x), u2h(p2u.y), u2h(p2u.z), u2h(p2u.w)};
        const uint4 P1arr[4] = {P1a0, P1a1, P1a2, P1a3};

        #pragma unroll
        for (int d = 0; d < 4; d++) {
            const __half2 p1j[4] = {u2h(P1arr[d].x), u2h(P1arr[d].y),
                                    u2h(P1arr[d].z), u2h(P1arr[d].w)};
            #pragma unroll
            for (int j = 0; j < 4; j++) {
                acc[d][j] = __hfma2(p0j[j], l0d[d], acc[d][j]);
                acc[d][j] = __hfma2(p1j[j], l1w,    acc[d][j]);
                acc[d][j] = __hfma2(l2j[j], p2d[d], acc[d][j]);
            }
        }

        P0a = P0n; L2a = L2n;
        P1a0 = P1n0; P1a1 = P1n1; P1a2 = P1n2; P1a3 = P1n3;
    }

    // ---- epilogue (round-9 proven): per-sg half2 at offset sg in uint4 ----
    #pragma unroll
    for (int d = 0; d < 4; d++) {
        unsigned* base = reinterpret_cast<unsigned*>(g_T)
                       + ((((size_t)(a2b + d)) * GRES + a1) * GRES + a0) * 4 + sg;
        #pragma unroll
        for (int j = 0; j < 4; j++)
            base[j * 4] = h2u(acc[d][j]);
    }
}

// ---------------------------------------------------------------------------
// Sample + Rodrigues: one thread per point; 8 LDG.128 trilinear gathers.
// ---------------------------------------------------------------------------
__device__ __forceinline__ void unp6(uint4 q, float f[6]) {
    float2 a = __half22float2(u2h(q.x));
    float2 b = __half22float2(u2h(q.y));
    float2 c = __half22float2(u2h(q.z));
    f[0] = a.x; f[1] = a.y; f[2] = b.x; f[3] = b.y; f[4] = c.x; f[5] = c.y;
}

__global__ __launch_bounds__(256)
void sample_warp(const float* __restrict__ xyz, const float* __restrict__ vd,
                 const float* __restrict__ aabb, float* __restrict__ out,
                 int npts) {
    int pt = blockIdx.x * 256 + threadIdx.x;
    if (pt >= npts) return;

    const float X0 = xyz[pt * 3 + 0], X1 = xyz[pt * 3 + 1], X2 = xyz[pt * 3 + 2];
    const float Pc[3] = {X0, X1, X2};

    int ii[2][3];
    float w[3];
    #pragma unroll
    for (int d = 0; d < 3; d++) {
        float lo = __ldg(&aabb[d]), hi = __ldg(&aabb[3 + d]);
        float xn = (Pc[d] - lo) * (2.0f / (hi - lo)) - 1.0f;
        float f = fmaf(xn, 63.5f, 63.5f);
        f = fminf(fmaxf(f, 0.0f), 127.0f);
        float ff = floorf(f);
        ii[0][d] = (int)ff;
        ii[1][d] = min(ii[0][d] + 1, GRES - 1);
        w[d] = f - ff;
    }

    float f[2][2][2][6];
    #pragma unroll
    for (int c2 = 0; c2 < 2; c2++)
        #pragma unroll
        for (int c1 = 0; c1 < 2; c1++)
            #pragma unroll
            for (int c0 = 0; c0 < 2; c0++) {
                uint4 q = __ldg(&g_T[((size_t)ii[c2][2] * GRES + ii[c1][1]) * GRES
                                     + ii[c0][0]]);
                unp6(q, f[c2][c1][c0]);
            }

    float bw[6];
    #pragma unroll
    for (int j = 0; j < 6; j++) {
        float e00 = fmaf(w[0], f[0][0][1][j] - f[0][0][0][j], f[0][0][0][j]);
        float e01 = fmaf(w[0], f[0][1][1][j] - f[0][1][0][j], f[0][1][0][j]);
        float e10 = fmaf(w[0], f[1][0][1][j] - f[1][0][0][j], f[1][0][0][j]);
        float e11 = fmaf(w[0], f[1][1][1][j] - f[1][1][0][j], f[1][1][0][j]);
        float g0  = fmaf(w[1], e01 - e00, e00);
        float g1  = fmaf(w[1], e11 - e10, e10);
        bw[j] = fmaf(w[2], g1 - g0, g0);
    }

    float w0 = bw[0], w1 = bw[1], w2 = bw[2];
    float v0 = bw[3], v1 = bw[4], v2 = bw[5];

    float th2 = fmaf(w0, w0, fmaf(w1, w1, w2 * w2));
    th2 = fmaxf(th2, 1e-6f);
    float th  = sqrtf(th2);
    float inv = 1.0f / th;
    w0 *= inv; w1 *= inv; w2 *= inv;
    v0 *= inv; v1 *= inv; v2 *= inv;

    float q  = fmaf(w0, w0, fmaf(w1, w1, w2 * w2));
    float s  = sinf(th);
    float co = cosf(th);
    float cm = 1.0f - co;
    float ts = th - s;

    float rD = 1.0f - cm * q;
    float pD = th - ts * q;

    float D0 = vd[pt * 3 + 0], D1 = vd[pt * 3 + 1], D2 = vd[pt * 3 + 2];

    float wdV = fmaf(w0, v0, fmaf(w1, v1, w2 * v2));
    float t0 = pD * v0 + cm * (w1 * v2 - w2 * v1) + ts * w0 * wdV;
    float t1 = pD * v1 + cm * (w2 * v0 - w0 * v2) + ts * w1 * wdV;
    float t2 = pD * v2 + cm * (w0 * v1 - w1 * v0) + ts * w2 * wdV;

    float wdX = fmaf(w0, X0, fmaf(w1, X1, w2 * X2));
    float xw0 = rD * X0 + s * (w1 * X2 - w2 * X1) + cm * w0 * wdX + t0;
    float xw1 = rD * X1 + s * (w2 * X0 - w0 * X2) + cm * w1 * wdX + t1;
    float xw2 = rD * X2 + s * (w0 * X1 - w1 * X0) + cm * w2 * wdX + t2;

    float wdD = fmaf(w0, D0, fmaf(w1, D1, w2 * D2));
    float vw0 = rD * D0 + s * (w1 * D2 - w2 * D1) + cm * w0 * wdD;
    float vw1 = rD * D1 + s * (w2 * D0 - w0 * D2) + cm * w1 * wdD;
    float vw2 = rD * D2 + s * (w0 * D1 - w1 * D0) + cm * w2 * wdD;

    out[(size_t)pt * 3 + 0] = xw0;
    out[(size_t)pt * 3 + 1] = xw1;
    out[(size_t)pt * 3 + 2] = xw2;
    size_t off = (size_t)npts * 3;
    out[off + (size_t)pt * 3 + 0] = vw0;
    out[off + (size_t)pt * 3 + 1] = vw1;
    out[off + (size_t)pt * 3 + 2] = vw2;
}

// ---------------------------------------------------------------------------
extern "C" void kernel_launch(void* const* d_in, const int* in_sizes, int n_in,
                              void* d_out, int out_size) {
    const float* xyz    = (const float*)d_in[0];
    const float* vdirs  = (const float*)d_in[1];
    const float* planes = (const float*)d_in[4];
    const float* lines  = (const float*)d_in[5];
    const float* aabb   = (const float*)d_in[6];
    float* out = (float*)d_out;

    const int npts = in_sizes[0] / 3;

    prep_ph<<<(2 * 3 * 16 * (NPIX / 2) + 255) / 256, 256>>>(planes);
    prep_lh<<<(3 * 16 * GRES + 255) / 256, 256>>>(lines);
    voxelize<<<dim3(GRES / 4, GRES / 4, 3), 128>>>(planes, lines);
    sample_warp<<<(npts + 255) / 256, 256>>>(xyz, vdirs, aabb, out, npts);
}

// round 12
// speedup vs baseline: 1.1369x; 1.0004x over previous
#include <cuda_runtime.h>
#include <cuda_fp16.h>
#include <math.h>

#define GRES 128
#define NPIX 16384
#define NVOX (GRES * GRES * GRES)

// Fused trilinear table: T[a2][a1][a0] -> uint4 (6 halves + pad). 33.5 MB.
__device__ uint4 g_T[NVOX];
// SoA accumulation tables: one half2(s0,s1) per voxel per s-group. 25 MB.
__device__ unsigned g_soa[3][NVOX];
// s-interleaved fp16 plane streams: [g(2)][sg(3)][c(16)][px] = half2(s0,s1). 6.3 MB
__device__ unsigned g_pH[2 * 3 * 16 * NPIX];
// s-interleaved fp16 line2 rows: [sg][c][a0] = half2(s0,s1). 24 KB
__device__ unsigned g_L2H[3 * 16 * GRES];

__device__ __forceinline__ __half2 u2h(unsigned u) {
    return *reinterpret_cast<__half2*>(&u);
}
__device__ __forceinline__ unsigned h2u(__half2 h) {
    return *reinterpret_cast<unsigned*>(&h);
}

// ---------------------------------------------------------------------------
// Prep: s-interleaved fp16 streams for plane groups 0,1.
// ---------------------------------------------------------------------------
__global__ void prep_ph(const float* __restrict__ planes) {
    int o = blockIdx.x * 256 + threadIdx.x;          // over 786432 pixel-pairs
    if (o >= 2 * 3 * 16 * (NPIX / 2)) return;
    int pp = o & 8191;
    int t  = o >> 13;
    int c  = t & 15;  t >>= 4;
    int sg = t % 3;
    int g  = t / 3;
    const float2* s0 = (const float2*)(planes + ((size_t)(g * 96 + (2 * sg) * 16 + c) << 14)) + pp;
    const float2* s1 = (const float2*)(planes + ((size_t)(g * 96 + (2 * sg + 1) * 16 + c) << 14)) + pp;
    float2 v0 = __ldg(s0);
    float2 v1 = __ldg(s1);
    uint2 q;
    q.x = h2u(__floats2half2_rn(v0.x, v1.x));
    q.y = h2u(__floats2half2_rn(v0.y, v1.y));
    reinterpret_cast<uint2*>(g_pH)[((g * 3 + sg) * 16 + c) * 8192 + pp] = q;
}

__global__ void prep_lh(const float* __restrict__ lines) {
    int o = blockIdx.x * 256 + threadIdx.x;          // over 6144
    if (o >= 3 * 16 * GRES) return;
    int x = o & 127;
    int c = (o >> 7) & 15;
    int sg = o >> 11;
    float v0 = __ldg(&lines[(size_t)(192 + (2 * sg) * 16 + c) * GRES + x]);
    float v1 = __ldg(&lines[(size_t)(192 + (2 * sg + 1) * 16 + c) * GRES + x]);
    g_L2H[o] = h2u(__floats2half2_rn(v0, v1));
}

// ---------------------------------------------------------------------------
// Voxelize, all-fp16 HFMA2, s-interleaved (grid.z = sg), 4 a1 x 8 a2 tile:
//   T[a2][a1][a0][s] = sum_c plane0[sc][a1][a0]*line0[sc][a2]
//                    + plane1[sc][a2][a0]*line1[sc][a1]
//                    + plane2[sc][a2][a1]*line2[sc][a0]
// Block = 128 thr = 4 warps (one a1 each) sharing an 8-wide a2 tile (halves
// P0 re-reads vs 4-wide; P1 rows block-shared via L1). Writes go to SoA
// tables as contiguous STG.128 — zero write-sector amplification.
// ---------------------------------------------------------------------------
__global__ __launch_bounds__(128)
void voxelize(const float* __restrict__ planes, const float* __restrict__ lines) {
    __shared__ __align__(16) __half2 s_l0[16][8];      // [c][d]   line0 splat
    __shared__ __align__(16) __half2 s_l1[16][4];      // [c][wid] line1 splat
    __shared__ __align__(16) __half2 s_p2[16][4][8];   // [c][wid][d] plane2 splat

    const int tid  = threadIdx.x;
    const int lane = tid & 31;
    const int wid  = tid >> 5;             // local a1 (0..3)
    const int a1b  = blockIdx.x * 4;
    const int a2b  = blockIdx.y * 8;
    const int sg   = blockIdx.z;           // s-group: s = 2sg, 2sg+1
    const int a1   = a1b + wid;
    const int a0   = lane * 4;

    // ---- one-time staging of scalar splats ----
    {
        int c = tid >> 3, d = tid & 7;                 // l0: 16x8 = 128 entries
        int sc0 = (2 * sg) * 16 + c, sc1 = sc0 + 16;
        float v0 = lines[(size_t)sc0 * GRES + a2b + d];
        float v1 = lines[(size_t)sc1 * GRES + a2b + d];
        s_l0[c][d] = __floats2half2_rn(v0, v1);
    }
    if (tid < 64) {                                    // l1: 16x4
        int c = tid >> 2, d = tid & 3;
        int sc0 = (2 * sg) * 16 + c, sc1 = sc0 + 16;
        float v0 = lines[(size_t)(96 + sc0) * GRES + a1b + d];
        float v1 = lines[(size_t)(96 + sc1) * GRES + a1b + d];
        s_l1[c][d] = __floats2half2_rn(v0, v1);
    }
    for (int i = tid; i < 512; i += 128) {             // p2: [c][w][d] 16x4x8
        int d = i & 7, w = (i >> 3) & 3, c = i >> 5;
        int sc0 = (2 * sg) * 16 + c, sc1 = sc0 + 16;
        float v0 = planes[(size_t)(192 + sc0) * NPIX + (a2b + d) * GRES + (a1b + w)];
        float v1 = planes[(size_t)(192 + sc1) * NPIX + (a2b + d) * GRES + (a1b + w)];
        s_p2[c][w][d] = __floats2half2_rn(v0, v1);
    }
    __syncthreads();

    __half2 acc[8][4];                     // [d = a2 local][j = a0 offset]
    #pragma unroll
    for (int d = 0; d < 8; d++)
        #pragma unroll
        for (int j = 0; j < 4; j++)
            acc[d][j] = __floats2half2_rn(0.0f, 0.0f);

    const unsigned* __restrict__ P0b = g_pH + (((size_t)sg * 16) << 14);
    const unsigned* __restrict__ P1b = g_pH + (((size_t)(48 + sg * 16)) << 14);
    const unsigned* __restrict__ L2b = g_L2H + sg * 16 * GRES;

    #pragma unroll 4
    for (int c = 0; c < 16; c++) {
        const size_t off = ((size_t)c) << 14;
        uint4 P0  = __ldg((const uint4*)(P0b + off + a1 * GRES + a0));
        uint4 L2v = __ldg((const uint4*)(L2b + c * GRES + a0));

        const __half2 p0j[4] = {u2h(P0.x), u2h(P0.y), u2h(P0.z), u2h(P0.w)};
        const __half2 l2j[4] = {u2h(L2v.x), u2h(L2v.y), u2h(L2v.z), u2h(L2v.w)};
        const __half2 l1w = s_l1[c][wid];              // warp-uniform

        #pragma unroll
        for (int d = 0; d < 8; d++) {
            uint4 P1 = __ldg((const uint4*)(P1b + off + (a2b + d) * GRES + a0));
            const __half2 p1j[4] = {u2h(P1.x), u2h(P1.y), u2h(P1.z), u2h(P1.w)};
            const __half2 l0d = s_l0[c][d];            // warp-uniform
            const __half2 p2d = s_p2[c][wid][d];       // warp-uniform
            #pragma unroll
            for (int j = 0; j < 4; j++) {
                acc[d][j] = __hfma2(p0j[j], l0d, acc[d][j]);
                acc[d][j] = __hfma2(p1j[j], l1w, acc[d][j]);
                acc[d][j] = __hfma2(l2j[j], p2d, acc[d][j]);
            }
        }
    }

    // ---- epilogue: contiguous STG.128 into SoA table (no amplification) ----
    #pragma unroll
    for (int d = 0; d < 8; d++) {
        uint4 q;
        q.x = h2u(acc[d][0]); q.y = h2u(acc[d][1]);
        q.z = h2u(acc[d][2]); q.w = h2u(acc[d][3]);
        int vox = ((a2b + d) * GRES + a1) * GRES + a0;
        *(uint4*)&g_soa[sg][vox] = q;
    }
}

// ---------------------------------------------------------------------------
// Repack: SoA (3 x 4B/voxel) -> AoS uint4 records. Fully coalesced.
// ---------------------------------------------------------------------------
__global__ void repack() {
    int t = blockIdx.x * 256 + threadIdx.x;
    if (t >= NVOX) return;
    uint4 q;
    q.x = g_soa[0][t];
    q.y = g_soa[1][t];
    q.z = g_soa[2][t];
    q.w = 0u;
    g_T[t] = q;
}

// ---------------------------------------------------------------------------
// Sample + Rodrigues: one thread per point; 8 LDG.128 trilinear gathers.
// ---------------------------------------------------------------------------
__device__ __forceinline__ void unp6(uint4 q, float f[6]) {
    float2 a = __half22float2(u2h(q.x));
    float2 b = __half22float2(u2h(q.y));
    float2 c = __half22float2(u2h(q.z));
    f[0] = a.x; f[1] = a.y; f[2] = b.x; f[3] = b.y; f[4] = c.x; f[5] = c.y;
}

__global__ __launch_bounds__(256)
void sample_warp(const float* __restrict__ xyz, const float* __restrict__ vd,
                 const float* __restrict__ aabb, float* __restrict__ out,
                 int npts) {
    int pt = blockIdx.x * 256 + threadIdx.x;
    if (pt >= npts) return;

    const float X0 = xyz[pt * 3 + 0], X1 = xyz[pt * 3 + 1], X2 = xyz[pt * 3 + 2];
    const float Pc[3] = {X0, X1, X2};

    int ii[2][3];
    float w[3];
    #pragma unroll
    for (int d = 0; d < 3; d++) {
        float lo = __ldg(&aabb[d]), hi = __ldg(&aabb[3 + d]);
        float xn = (Pc[d] - lo) * (2.0f / (hi - lo)) - 1.0f;
        float f = fmaf(xn, 63.5f, 63.5f);
        f = fminf(fmaxf(f, 0.0f), 127.0f);
        float ff = floorf(f);
        ii[0][d] = (int)ff;
        ii[1][d] = min(ii[0][d] + 1, GRES - 1);
        w[d] = f - ff;
    }

    float f[2][2][2][6];
    #pragma unroll
    for (int c2 = 0; c2 < 2; c2++)
        #pragma unroll
        for (int c1 = 0; c1 < 2; c1++)
            #pragma unroll
            for (int c0 = 0; c0 < 2; c0++) {
                uint4 q = __ldg(&g_T[((size_t)ii[c2][2] * GRES + ii[c1][1]) * GRES
                                     + ii[c0][0]]);
                unp6(q, f[c2][c1][c0]);
            }

    float bw[6];
    #pragma unroll
    for (int j = 0; j < 6; j++) {
        float e00 = fmaf(w[0], f[0][0][1][j] - f[0][0][0][j], f[0][0][0][j]);
        float e01 = fmaf(w[0], f[0][1][1][j] - f[0][1][0][j], f[0][1][0][j]);
        float e10 = fmaf(w[0], f[1][0][1][j] - f[1][0][0][j], f[1][0][0][j]);
        float e11 = fmaf(w[0], f[1][1][1][j] - f[1][1][0][j], f[1][1][0][j]);
        float g0  = fmaf(w[1], e01 - e00, e00);
        float g1  = fmaf(w[1], e11 - e10, e10);
        bw[j] = fmaf(w[2], g1 - g0, g0);
    }

    float w0 = bw[0], w1 = bw[1], w2 = bw[2];
    float v0 = bw[3], v1 = bw[4], v2 = bw[5];

    float th2 = fmaf(w0, w0, fmaf(w1, w1, w2 * w2));
    th2 = fmaxf(th2, 1e-6f);
    float th  = sqrtf(th2);
    float inv = 1.0f / th;
    w0 *= inv; w1 *= inv; w2 *= inv;
    v0 *= inv; v1 *= inv; v2 *= inv;

    float q  = fmaf(w0, w0, fmaf(w1, w1, w2 * w2));
    float s  = sinf(th);
    float co = cosf(th);
    float cm = 1.0f - co;
    float ts = th - s;

    float rD = 1.0f - cm * q;
    float pD = th - ts * q;

    float D0 = vd[pt * 3 + 0], D1 = vd[pt * 3 + 1], D2 = vd[pt * 3 + 2];

    float wdV = fmaf(w0, v0, fmaf(w1, v1, w2 * v2));
    float t0 = pD * v0 + cm * (w1 * v2 - w2 * v1) + ts * w0 * wdV;
    float t1 = pD * v1 + cm * (w2 * v0 - w0 * v2) + ts * w1 * wdV;
    float t2 = pD * v2 + cm * (w0 * v1 - w1 * v0) + ts * w2 * wdV;

    float wdX = fmaf(w0, X0, fmaf(w1, X1, w2 * X2));
    float xw0 = rD * X0 + s * (w1 * X2 - w2 * X1) + cm * w0 * wdX + t0;
    float xw1 = rD * X1 + s * (w2 * X0 - w0 * X2) + cm * w1 * wdX + t1;
    float xw2 = rD * X2 + s * (w0 * X1 - w1 * X0) + cm * w2 * wdX + t2;

    float wdD = fmaf(w0, D0, fmaf(w1, D1, w2 * D2));
    float vw0 = rD * D0 + s * (w1 * D2 - w2 * D1) + cm * w0 * wdD;
    float vw1 = rD * D1 + s * (w2 * D0 - w0 * D2) + cm * w1 * wdD;
    float vw2 = rD * D2 + s * (w0 * D1 - w1 * D0) + cm * w2 * wdD;

    out[(size_t)pt * 3 + 0] = xw0;
    out[(size_t)pt * 3 + 1] = xw1;
    out[(size_t)pt * 3 + 2] = xw2;
    size_t off = (size_t)npts * 3;
    out[off + (size_t)pt * 3 + 0] = vw0;
    out[off + (size_t)pt * 3 + 1] = vw1;
    out[off + (size_t)pt * 3 + 2] = vw2;
}

// ---------------------------------------------------------------------------
extern "C" void kernel_launch(void* const* d_in, const int* in_sizes, int n_in,
                              void* d_out, int out_size) {
    const float* xyz    = (const float*)d_in[0];
    const float* vdirs  = (const float*)d_in[1];
    const float* planes = (const float*)d_in[4];
    const float* lines  = (const float*)d_in[5];
    const float* aabb   = (const float*)d_in[6];
    float* out = (float*)d_out;

    const int npts = in_sizes[0] / 3;

    prep_ph<<<(2 * 3 * 16 * (NPIX / 2) + 255) / 256, 256>>>(planes);
    prep_lh<<<(3 * 16 * GRES + 255) / 256, 256>>>(lines);
    voxelize<<<dim3(GRES / 4, GRES / 8, 3), 128>>>(planes, lines);
    repack<<<(NVOX + 255) / 256, 256>>>();
    sample_warp<<<(npts + 255) / 256, 256>>>(xyz, vdirs, aabb, out, npts);
}

// round 14
// speedup vs baseline: 1.2439x; 1.0941x over previous
#include <cuda_runtime.h>
#include <cuda_fp16.h>
#include <math.h>

#define GRES 128
#define NPIX 16384
#define NVOX (GRES * GRES * GRES)

// Fused trilinear table: T[a2][a1][a0] -> uint4 (6 halves + pad). 33.5 MB.
__device__ uint4 g_T[NVOX];
// SoA accumulation tables: one half2(s0,s1) per voxel per s-group. 25 MB.
__device__ unsigned g_soa[3][NVOX];
// s-interleaved fp16 plane streams: [g(2)][sg(3)][c(16)][px] = half2(s0,s1). 6.3 MB
__device__ unsigned g_pH[2 * 3 * 16 * NPIX];
// s-interleaved fp16 line2 rows: [sg][c][a0] = half2(s0,s1). 24 KB
__device__ unsigned g_L2H[3 * 16 * GRES];

__device__ __forceinline__ __half2 u2h(unsigned u) {
    return *reinterpret_cast<__half2*>(&u);
}
__device__ __forceinline__ unsigned h2u(__half2 h) {
    return *reinterpret_cast<unsigned*>(&h);
}

// ---------------------------------------------------------------------------
// Merged prep: s-interleaved fp16 plane streams (8 px/thread, vectorized)
// + line2 rows. 96 plane streams (2 g x 3 sg x 16 c) x 2048 groups.
// ---------------------------------------------------------------------------
#define PREP_PLANE_ITEMS (96 * 2048)

__global__ void prep(const float* __restrict__ planes,
                     const float* __restrict__ lines) {
    int o = blockIdx.x * 256 + threadIdx.x;
    if (o < PREP_PLANE_ITEMS) {
        int pp4 = o & 2047;                // group of 8 pixels
        int t   = o >> 11;                 // stream id 0..95
        int c   = t & 15;  t >>= 4;        // t in [0,6)
        int sg  = t % 3;
        int g   = t / 3;
        const float4* s0 = (const float4*)(planes +
            ((size_t)(g * 96 + (2 * sg) * 16 + c) << 14)) + pp4 * 2;
        const float4* s1 = (const float4*)(planes +
            ((size_t)(g * 96 + (2 * sg + 1) * 16 + c) << 14)) + pp4 * 2;
        float4 a0 = __ldg(s0),     b0 = __ldg(s0 + 1);
        float4 a1 = __ldg(s1),     b1 = __ldg(s1 + 1);
        uint4 q0, q1;
        q0.x = h2u(__floats2half2_rn(a0.x, a1.x));
        q0.y = h2u(__floats2half2_rn(a0.y, a1.y));
        q0.z = h2u(__floats2half2_rn(a0.z, a1.z));
        q0.w = h2u(__floats2half2_rn(a0.w, a1.w));
        q1.x = h2u(__floats2half2_rn(b0.x, b1.x));
        q1.y = h2u(__floats2half2_rn(b0.y, b1.y));
        q1.z = h2u(__floats2half2_rn(b0.z, b1.z));
        q1.w = h2u(__floats2half2_rn(b0.w, b1.w));
        int st = (g * 3 + sg) * 16 + c;
        uint4* dst = (uint4*)(g_pH + ((size_t)st << 14)) + pp4 * 2;
        dst[0] = q0;
        dst[1] = q1;
    } else if (o < PREP_PLANE_ITEMS + 6144) {   // line2 rows
        int o2 = o - PREP_PLANE_ITEMS;
        int x = o2 & 127;
        int c = (o2 >> 7) & 15;
        int sg = o2 >> 11;
        float v0 = __ldg(&lines[(size_t)(192 + (2 * sg) * 16 + c) * GRES + x]);
        float v1 = __ldg(&lines[(size_t)(192 + (2 * sg + 1) * 16 + c) * GRES + x]);
        g_L2H[o2] = h2u(__floats2half2_rn(v0, v1));
    }
}

// ---------------------------------------------------------------------------
// Voxelize, all-fp16 HFMA2, s-interleaved (grid.z = sg), 4 a1 x 8 a2 tile:
//   T[a2][a1][a0][s] = sum_c plane0[sc][a1][a0]*line0[sc][a2]
//                    + plane1[sc][a2][a0]*line1[sc][a1]
//                    + plane2[sc][a2][a1]*line2[sc][a0]
// P1 loads batched in groups of 4 before their compute (fewer stall points).
// Writes: contiguous STG.128 into SoA tables (no amplification).
// ---------------------------------------------------------------------------
__global__ __launch_bounds__(128)
void voxelize(const float* __restrict__ planes, const float* __restrict__ lines) {
    __shared__ __align__(16) __half2 s_l0[16][8];      // [c][d]   line0 splat
    __shared__ __align__(16) __half2 s_l1[16][4];      // [c][wid] line1 splat
    __shared__ __align__(16) __half2 s_p2[16][4][8];   // [c][wid][d] plane2 splat

    const int tid  = threadIdx.x;
    const int lane = tid & 31;
    const int wid  = tid >> 5;             // local a1 (0..3)
    const int a1b  = blockIdx.x * 4;
    const int a2b  = blockIdx.y * 8;
    const int sg   = blockIdx.z;           // s-group: s = 2sg, 2sg+1
    const int a1   = a1b + wid;
    const int a0   = lane * 4;

    // ---- one-time staging of scalar splats ----
    {
        int c = tid >> 3, d = tid & 7;                 // l0: 16x8 = 128 entries
        int sc0 = (2 * sg) * 16 + c, sc1 = sc0 + 16;
        float v0 = lines[(size_t)sc0 * GRES + a2b + d];
        float v1 = lines[(size_t)sc1 * GRES + a2b + d];
        s_l0[c][d] = __floats2half2_rn(v0, v1);
    }
    if (tid < 64) {                                    // l1: 16x4
        int c = tid >> 2, d = tid & 3;
        int sc0 = (2 * sg) * 16 + c, sc1 = sc0 + 16;
        float v0 = lines[(size_t)(96 + sc0) * GRES + a1b + d];
        float v1 = lines[(size_t)(96 + sc1) * GRES + a1b + d];
        s_l1[c][d] = __floats2half2_rn(v0, v1);
    }
    for (int i = tid; i < 512; i += 128) {             // p2: [c][w][d] 16x4x8
        int d = i & 7, w = (i >> 3) & 3, c = i >> 5;
        int sc0 = (2 * sg) * 16 + c, sc1 = sc0 + 16;
        float v0 = planes[(size_t)(192 + sc0) * NPIX + (a2b + d) * GRES + (a1b + w)];
        float v1 = planes[(size_t)(192 + sc1) * NPIX + (a2b + d) * GRES + (a1b + w)];
        s_p2[c][w][d] = __floats2half2_rn(v0, v1);
    }
    __syncthreads();

    __half2 acc[8][4];                     // [d = a2 local][j = a0 offset]
    #pragma unroll
    for (int d = 0; d < 8; d++)
        #pragma unroll
        for (int j = 0; j < 4; j++)
            acc[d][j] = __floats2half2_rn(0.0f, 0.0f);

    const unsigned* __restrict__ P0b = g_pH + (((size_t)sg * 16) << 14);
    const unsigned* __restrict__ P1b = g_pH + (((size_t)(48 + sg * 16)) << 14);
    const unsigned* __restrict__ L2b = g_L2H + sg * 16 * GRES;

    #pragma unroll 4
    for (int c = 0; c < 16; c++) {
        const size_t off = ((size_t)c) << 14;
        uint4 P0  = __ldg((const uint4*)(P0b + off + a1 * GRES + a0));
        uint4 L2v = __ldg((const uint4*)(L2b + c * GRES + a0));

        const __half2 p0j[4] = {u2h(P0.x), u2h(P0.y), u2h(P0.z), u2h(P0.w)};
        const __half2 l2j[4] = {u2h(L2v.x), u2h(L2v.y), u2h(L2v.z), u2h(L2v.w)};
        const __half2 l1w = s_l1[c][wid];              // warp-uniform

        #pragma unroll
        for (int half = 0; half < 2; half++) {
            uint4 P1r[4];
            #pragma unroll
            for (int k = 0; k < 4; k++)
                P1r[k] = __ldg((const uint4*)(P1b + off +
                               (a2b + half * 4 + k) * GRES + a0));
            #pragma unroll
            for (int k = 0; k < 4; k++) {
                const int d = half * 4 + k;
                const __half2 p1j[4] = {u2h(P1r[k].x), u2h(P1r[k].y),
                                        u2h(P1r[k].z), u2h(P1r[k].w)};
                const __half2 l0d = s_l0[c][d];        // warp-uniform
                const __half2 p2d = s_p2[c][wid][d];   // warp-uniform
                #pragma unroll
                for (int j = 0; j < 4; j++) {
                    acc[d][j] = __hfma2(p0j[j], l0d, acc[d][j]);
                    acc[d][j] = __hfma2(p1j[j], l1w, acc[d][j]);
                    acc[d][j] = __hfma2(l2j[j], p2d, acc[d][j]);
                }
            }
        }
    }

    // ---- epilogue: contiguous STG.128 into SoA table (no amplification) ----
    #pragma unroll
    for (int d = 0; d < 8; d++) {
        uint4 q;
        q.x = h2u(acc[d][0]); q.y = h2u(acc[d][1]);
        q.z = h2u(acc[d][2]); q.w = h2u(acc[d][3]);
        int vox = ((a2b + d) * GRES + a1) * GRES + a0;
        *(uint4*)&g_soa[sg][vox] = q;
    }
}

// ---------------------------------------------------------------------------
// Repack: SoA (3 x 4B/voxel) -> AoS uint4. 4 voxels/thread, MLP=12,
// all accesses dense/coalesced.
// ---------------------------------------------------------------------------
__global__ void repack() {
    int base = blockIdx.x * 1024 + threadIdx.x;
    unsigned x[4], y[4], z[4];
    #pragma unroll
    for (int k = 0; k < 4; k++) x[k] = __ldg(&g_soa[0][base + k * 256]);
    #pragma unroll
    for (int k = 0; k < 4; k++) y[k] = __ldg(&g_soa[1][base + k * 256]);
    #pragma unroll
    for (int k = 0; k < 4; k++) z[k] = __ldg(&g_soa[2][base + k * 256]);
    #pragma unroll
    for (int k = 0; k < 4; k++) {
        uint4 q;
        q.x = x[k]; q.y = y[k]; q.z = z[k]; q.w = 0u;
        g_T[base + k * 256] = q;
    }
}

// ---------------------------------------------------------------------------
// Sample + Rodrigues: one thread per point; 8 LDG.128 trilinear gathers.
// ---------------------------------------------------------------------------
__device__ __forceinline__ void unp6(uint4 q, float f[6]) {
    float2 a = __half22float2(u2h(q.x));
    float2 b = __half22float2(u2h(q.y));
    float2 c = __half22float2(u2h(q.z));
    f[0] = a.x; f[1] = a.y; f[2] = b.x; f[3] = b.y; f[4] = c.x; f[5] = c.y;
}

__global__ __launch_bounds__(256)
void sample_warp(const float* __restrict__ xyz, const float* __restrict__ vd,
                 const float* __restrict__ aabb, float* __restrict__ out,
                 int npts) {
    int pt = blockIdx.x * 256 + threadIdx.x;
    if (pt >= npts) return;

    const float X0 = xyz[pt * 3 + 0], X1 = xyz[pt * 3 + 1], X2 = xyz[pt * 3 + 2];
    const float Pc[3] = {X0, X1, X2};

    int ii[2][3];
    float w[3];
    #pragma unroll
    for (int d = 0; d < 3; d++) {
        float lo = __ldg(&aabb[d]), hi = __ldg(&aabb[3 + d]);
        float xn = (Pc[d] - lo) * (2.0f / (hi - lo)) - 1.0f;
        float f = fmaf(xn, 63.5f, 63.5f);
        f = fminf(fmaxf(f, 0.0f), 127.0f);
        float ff = floorf(f);
        ii[0][d] = (int)ff;
        ii[1][d] = min(ii[0][d] + 1, GRES - 1);
        w[d] = f - ff;
    }

    float f[2][2][2][6];
    #pragma unroll
    for (int c2 = 0; c2 < 2; c2++)
        #pragma unroll
        for (int c1 = 0; c1 < 2; c1++)
            #pragma unroll
            for (int c0 = 0; c0 < 2; c0++) {
                uint4 q = __ldg(&g_T[((size_t)ii[c2][2] * GRES + ii[c1][1]) * GRES
                                     + ii[c0][0]]);
                unp6(q, f[c2][c1][c0]);
            }

    float bw[6];
    #pragma unroll
    for (int j = 0; j < 6; j++) {
        float e00 = fmaf(w[0], f[0][0][1][j] - f[0][0][0][j], f[0][0][0][j]);
        float e01 = fmaf(w[0], f[0][1][1][j] - f[0][1][0][j], f[0][1][0][j]);
        float e10 = fmaf(w[0], f[1][0][1][j] - f[1][0][0][j], f[1][0][0][j]);
        float e11 = fmaf(w[0], f[1][1][1][j] - f[1][1][0][j], f[1][1][0][j]);
        float g0  = fmaf(w[1], e01 - e00, e00);
        float g1  = fmaf(w[1], e11 - e10, e10);
        bw[j] = fmaf(w[2], g1 - g0, g0);
    }

    float w0 = bw[0], w1 = bw[1], w2 = bw[2];
    float v0 = bw[3], v1 = bw[4], v2 = bw[5];

    float th2 = fmaf(w0, w0, fmaf(w1, w1, w2 * w2));
    th2 = fmaxf(th2, 1e-6f);
    float th  = sqrtf(th2);
    float inv = 1.0f / th;
    w0 *= inv; w1 *= inv; w2 *= inv;
    v0 *= inv; v1 *= inv; v2 *= inv;

    float q  = fmaf(w0, w0, fmaf(w1, w1, w2 * w2));
    float s  = sinf(th);
    float co = cosf(th);
    float cm = 1.0f - co;
    float ts = th - s;

    float rD = 1.0f - cm * q;
    float pD = th - ts * q;

    float D0 = vd[pt * 3 + 0], D1 = vd[pt * 3 + 1], D2 = vd[pt * 3 + 2];

    float wdV = fmaf(w0, v0, fmaf(w1, v1, w2 * v2));
    float t0 = pD * v0 + cm * (w1 * v2 - w2 * v1) + ts * w0 * wdV;
    float t1 = pD * v1 + cm * (w2 * v0 - w0 * v2) + ts * w1 * wdV;
    float t2 = pD * v2 + cm * (w0 * v1 - w1 * v0) + ts * w2 * wdV;

    float wdX = fmaf(w0, X0, fmaf(w1, X1, w2 * X2));
    float xw0 = rD * X0 + s * (w1 * X2 - w2 * X1) + cm * w0 * wdX + t0;
    float xw1 = rD * X1 + s * (w2 * X0 - w0 * X2) + cm * w1 * wdX + t1;
    float xw2 = rD * X2 + s * (w0 * X1 - w1 * X0) + cm * w2 * wdX + t2;

    float wdD = fmaf(w0, D0, fmaf(w1, D1, w2 * D2));
    float vw0 = rD * D0 + s * (w1 * D2 - w2 * D1) + cm * w0 * wdD;
    float vw1 = rD * D1 + s * (w2 * D0 - w0 * D2) + cm * w1 * wdD;
    float vw2 = rD * D2 + s * (w0 * D1 - w1 * D0) + cm * w2 * wdD;

    out[(size_t)pt * 3 + 0] = xw0;
    out[(size_t)pt * 3 + 1] = xw1;
    out[(size_t)pt * 3 + 2] = xw2;
    size_t off = (size_t)npts * 3;
    out[off + (size_t)pt * 3 + 0] = vw0;
    out[off + (size_t)pt * 3 + 1] = vw1;
    out[off + (size_t)pt * 3 + 2] = vw2;
}

// ---------------------------------------------------------------------------
extern "C" void kernel_launch(void* const* d_in, const int* in_sizes, int n_in,
                              void* d_out, int out_size) {
    const float* xyz    = (const float*)d_in[0];
    const float* vdirs  = (const float*)d_in[1];
    const float* planes = (const float*)d_in[4];
    const float* lines  = (const float*)d_in[5];
    const float* aabb   = (const float*)d_in[6];
    float* out = (float*)d_out;

    const int npts = in_sizes[0] / 3;

    prep<<<(PREP_PLANE_ITEMS + 6144 + 255) / 256, 256>>>(planes, lines);
    voxelize<<<dim3(GRES / 4, GRES / 8, 3), 128>>>(planes, lines);
    repack<<<NVOX / 1024, 256>>>();
    sample_warp<<<(npts + 255) / 256, 256>>>(xyz, vdirs, aabb, out, npts);
}